// round 5
// baseline (speedup 1.0000x reference)
#include <cuda_runtime.h>
#include <cuda_bf16.h>

// BALayer association: n_img-hop min-label propagation + rank compaction.
// Reference semantics: leading[j] = min node index within graph distance
// <= n_img of j (nonzero pattern of A^n_img, unit diagonal);
// point_id = cumsum(leading==id)-1; out[j] = point_id[leading[j]] (f32).
//
// Fast path: chaotic in-place relaxation on packed (label<<6 | dist) with
// TWO relaxation rules per round:
//   edge (u,v): propose (label[v], dist[v]+1) to u (and symmetric)
//   jump  i   : propose (label[label[i]], dist[i]+dist[label[i]]) to i
// atomicMin orders by label then dist. Invariant: packed (L,d), d<63,
// implies L is within d hops. Both rules preserve it (saturation is
// conservative). At the fixed point labels = component min m and, by the
// edge-relaxation fixed-point property dist[u] <= dist[v]+1 plus the
// invariant, dist[u] == d(u,m) exactly. Certificate: max dist <= n_img
// everywhere  ==>  fixed point equals the n_img-hop answer bit-exactly.
// Otherwise fall back to exact synchronous Jacobi (n_img rounds).
// Pointer jumping makes rounds O(log dist) instead of O(dist).

#define NTHREADS 1024
#define EMAX 8          // register-cached edges per thread (M <= 8192)
#define DSHIFT 6        // dist bits
#define DMASK 63

__global__ __launch_bounds__(NTHREADS, 1)
void ba_assoc_kernel(const int* __restrict__ tracks, int M,
                     const int* __restrict__ n_img_ptr,
                     float* __restrict__ out, int N)
{
    extern __shared__ int sm[];
    int* cur  = sm;          // N packed labels (async) / labels (fallback)
    int* nxt  = sm + N;      // N labels, fallback double buffer + point_id
    int* scan = sm + 2 * N;  // NTHREADS/32 warp sums

    const int tid = threadIdx.x;
    const int nt  = blockDim.x;
    const int* __restrict__ t0 = tracks;
    const int* __restrict__ t1 = tracks + M;

    // Register-cache this thread's edges
    int eu[EMAX], ev[EMAX];
    int ne = 0;
    const bool cached = (M <= nt * EMAX);
    if (cached) {
        int m = tid;
        #pragma unroll
        for (int k = 0; k < EMAX; k++) {
            if (m < M) { eu[k] = t0[m]; ev[k] = t1[m]; ne++; m += nt; }
        }
    }
    const int iters = n_img_ptr ? *n_img_ptr : 16;

    // ---- Async phase: packed (label<<6 | dist), in-place relaxation ----
    for (int i = tid; i < N; i += nt) cur[i] = i << DSHIFT;  // dist 0
    __syncthreads();

    for (;;) {
        int changed = 0;

        // Edge relaxations
        if (cached) {
            #pragma unroll
            for (int k = 0; k < EMAX; k++) {
                if (k < ne) {
                    const int u = eu[k], v = ev[k];
                    const int pu = cur[u], pv = cur[v];
                    const int cv = pv + (int)((pv & DMASK) != DMASK);
                    const int cu = pu + (int)((pu & DMASK) != DMASK);
                    if (cv < pu) {
                        const int old = atomicMin(&cur[u], cv);
                        changed |= (old > cv);
                    } else if (cu < pv) {
                        const int old = atomicMin(&cur[v], cu);
                        changed |= (old > cu);
                    }
                }
            }
        } else {
            for (int m = tid; m < M; m += nt) {
                const int u = t0[m], v = t1[m];
                const int pu = cur[u], pv = cur[v];
                const int cv = pv + (int)((pv & DMASK) != DMASK);
                const int cu = pu + (int)((pu & DMASK) != DMASK);
                if (cv < pu) {
                    const int old = atomicMin(&cur[u], cv);
                    changed |= (old > cv);
                } else if (cu < pv) {
                    const int old = atomicMin(&cur[v], cu);
                    changed |= (old > cu);
                }
            }
        }

        // Pointer-jump relaxations: i -> label[i] -> label[label[i]]
        for (int i = tid; i < N; i += nt) {
            const int p = cur[i];
            const int L = p >> DSHIFT;
            if (L != i) {
                const int q  = cur[L];
                int ds = (p & DMASK) + (q & DMASK);
                if (ds > DMASK) ds = DMASK;
                const int c = (q & ~DMASK) | ds;   // (label[L], d+d2)
                if (c < p) {
                    const int old = atomicMin(&cur[i], c);
                    changed |= (old > c);
                }
            }
        }

        if (!__syncthreads_or(changed)) break;  // fixed point
    }

    // Certificate: every node's component-min within `iters` hops?
    int bad = 0;
    for (int i = tid; i < N; i += nt) bad |= ((cur[i] & DMASK) > iters);
    const int cert_fail = __syncthreads_or(bad);

    if (!cert_fail) {
        for (int i = tid; i < N; i += nt) cur[i] >>= DSHIFT;
        __syncthreads();
    } else {
        // ---- Exact fallback: synchronous Jacobi, `iters` rounds ----
        for (int i = tid; i < N; i += nt) cur[i] = i;
        __syncthreads();
        for (int it = 0; it < iters; ++it) {
            for (int i = tid; i < N; i += nt) nxt[i] = cur[i];
            __syncthreads();
            int changed = 0;
            for (int m = tid; m < M; m += nt) {
                const int u = t0[m], v = t1[m];
                const int lu = cur[u], lv = cur[v];
                if (lv < lu) {
                    const int old = atomicMin(&nxt[u], lv);
                    changed |= (old > lv);
                } else if (lu < lv) {
                    const int old = atomicMin(&nxt[v], lu);
                    changed |= (old > lu);
                }
            }
            const int any = __syncthreads_or(changed);
            int* tmp = cur; cur = nxt; nxt = tmp;
            if (!any) break;
        }
    }

    // ---- cur[j] = leading[j]. point_id over ALL indices, then gather ----
    const int per  = (N + nt - 1) / nt;
    const int base = tid * per;
    int cnt = 0;
    for (int k = 0; k < per; k++) {
        const int i = base + k;
        if (i < N) cnt += (cur[i] == i);
    }

    const int lane = tid & 31;
    const int wid  = tid >> 5;
    int x = cnt;
    #pragma unroll
    for (int o = 1; o < 32; o <<= 1) {
        int y = __shfl_up_sync(0xFFFFFFFFu, x, o);
        if (lane >= o) x += y;
    }
    if (lane == 31) scan[wid] = x;
    __syncthreads();
    if (wid == 0) {
        const int nwarps = nt >> 5;
        int w = (tid < nwarps) ? scan[tid] : 0;
        #pragma unroll
        for (int o = 1; o < 32; o <<= 1) {
            int y = __shfl_up_sync(0xFFFFFFFFu, w, o);
            if (lane >= o) w += y;
        }
        if (tid < nwarps) scan[tid] = w;
    }
    __syncthreads();

    int run = (x - cnt) + (wid ? scan[wid - 1] : 0);
    for (int k = 0; k < per; k++) {
        const int i = base + k;
        if (i < N) {
            run += (cur[i] == i);
            nxt[i] = run - 1;     // point_id
        }
    }
    __syncthreads();

    for (int i = tid; i < N; i += nt) out[i] = (float)nxt[cur[i]];
}

extern "C" void kernel_launch(void* const* d_in, const int* in_sizes, int n_in,
                              void* d_out, int out_size)
{
    const int* tracks = (const int*)d_in[4];
    const int  M      = in_sizes[4] / 2;
    const int  N      = in_sizes[2];
    const int* n_img  = (n_in >= 6 && in_sizes[5] == 1) ? (const int*)d_in[5]
                                                        : nullptr;
    float* out = (float*)d_out;

    const size_t shbytes = (size_t)(2 * N + (NTHREADS / 32)) * sizeof(int);
    ba_assoc_kernel<<<1, NTHREADS, shbytes>>>(tracks, M, n_img, out, N);
}